// round 10
// baseline (speedup 1.0000x reference)
#include <cuda_runtime.h>
#include <math.h>

#define N_CRIT   128
#define N_PAIRS  8128          // 128*127/2
#define N_TOT    8256          // N_CRIT + N_PAIRS
#define N_VEC4   2064          // N_TOT / 4
#define BATCH    16384
#define MIN_W    1e-7f
#define THREADS  512
#define ROWS_PER_BLOCK 4       // 16 warps: 4 warps per row
#define GRID     (BATCH / ROWS_PER_BLOCK)   // 4096, exact

__device__ float g_w[N_TOT];        // constrained weights (wc_eff ‖ wint_eff)
__device__ float g_partial[32];     // per-prep-block weight-sum partials

// quarter-row chunk starts/lengths in float4; all boundaries 128B-aligned
__constant__ int c_chunk_start[4] = {0, 528, 1040, 1552};
__constant__ int c_chunk_len[4]   = {528, 512, 512, 512};

// ---------------------------------------------------------------------------
// Prep: one pair per thread; per-block weight-sum partial into g_partial.
// grid = 32 x 256 (8192 >= 8128).
// ---------------------------------------------------------------------------
__global__ __launch_bounds__(256)
void prep_weights_kernel(const float* __restrict__ wc,
                         const float* __restrict__ wint) {
    __shared__ float s_wc[N_CRIT];
    __shared__ float s_red[256];

    const int tid = threadIdx.x;
    float local = 0.0f;

    if (tid < N_CRIT) {
        float w = wc[tid];
        w = (w < 0.0f) ? MIN_W : w;
        s_wc[tid] = w;
        if (blockIdx.x == 0) {
            g_w[tid] = w;
            local += w;
        }
    }
    __syncthreads();

    const int p = blockIdx.x * 256 + tid;
    if (p < N_PAIRS) {
        // invert start(i) = i*(255-i)/2 via sqrt + integer fixup
        float fi = (255.0f - sqrtf(65025.0f - 8.0f * (float)p)) * 0.5f;
        int i = (int)fi;
        if (i > 126) i = 126;
        if (i < 0) i = 0;
        while (i * (255 - i) / 2 > p) --i;
        while ((i + 1) * (254 - i) / 2 <= p) ++i;
        int j = p - i * (255 - i) / 2 + i + 1;

        float w = fmaxf(wint[p], fmaxf(-s_wc[i], -s_wc[j]));
        g_w[N_CRIT + p] = w;
        local += w;
    }

    s_red[tid] = local;
    __syncthreads();
    #pragma unroll
    for (int off = 128; off > 0; off >>= 1) {
        if (tid < off) s_red[tid] += s_red[tid + off];
        __syncthreads();
    }
    if (tid == 0) g_partial[blockIdx.x] = s_red[0];
}

// ---------------------------------------------------------------------------
// GEMV: 4096 blocks x 512 threads. 4 rows per block, 4 warps per row, each
// warp streams an aligned quarter-row chunk. Prologue: stage weights + warp-0
// reduces the 32 prep partials; single __syncthreads.
// ---------------------------------------------------------------------------
__global__ __launch_bounds__(THREADS, 4)
void choquet_gemv_kernel(const float* __restrict__ x,
                         const float* __restrict__ thr,
                         float* __restrict__ out) {
    __shared__ __align__(16) float s_w[N_TOT];   // 33 KB
    __shared__ float s_part[ROWS_PER_BLOCK][4];  // per-(row, quarter)
    __shared__ float s_inv;

    const int tid = threadIdx.x;

    // stage weights (coalesced float4)
    const float4* gw4 = reinterpret_cast<const float4*>(g_w);
    float4* sw4 = reinterpret_cast<float4*>(s_w);
    #pragma unroll
    for (int k = tid; k < N_VEC4; k += THREADS) {
        sw4[k] = gw4[k];
    }
    // warp 0: reduce the 32 prep partials (no block-wide reduction)
    if (tid < 32) {
        float v = g_partial[tid];
        #pragma unroll
        for (int off = 16; off > 0; off >>= 1) {
            v += __shfl_xor_sync(0xFFFFFFFFu, v, off);
        }
        if (tid == 0) s_inv = 1.0f / v;
    }
    __syncthreads();

    const int warp = tid >> 5;
    const int lane = tid & 31;
    const int row_local = warp >> 2;             // 0..3
    const int quarter   = warp & 3;              // 0..3
    const int row  = blockIdx.x * ROWS_PER_BLOCK + row_local;

    const int kstart = c_chunk_start[quarter];
    const int klen   = c_chunk_len[quarter];     // 528 or 512

    const float4* xr = reinterpret_cast<const float4*>(x) +
                       (size_t)row * N_VEC4;

    float acc = 0.0f;
    int k = kstart + lane;
    // 512/32 = 16 full iterations for all quarters
    #pragma unroll 4
    for (int it = 0; it < 16; ++it, k += 32) {
        float4 a = __ldcs(&xr[k]);               // streaming: read-once
        float4 b = sw4[k];
        acc = fmaf(a.x, b.x, acc);
        acc = fmaf(a.y, b.y, acc);
        acc = fmaf(a.z, b.z, acc);
        acc = fmaf(a.w, b.w, acc);
    }
    if (klen == 528 && lane < 16) {              // quarter 0 tail: 16 float4
        float4 a = __ldcs(&xr[k]);
        float4 b = sw4[k];
        acc = fmaf(a.x, b.x, acc);
        acc = fmaf(a.y, b.y, acc);
        acc = fmaf(a.z, b.z, acc);
        acc = fmaf(a.w, b.w, acc);
    }

    // warp reduce
    #pragma unroll
    for (int off = 16; off > 0; off >>= 1) {
        acc += __shfl_xor_sync(0xFFFFFFFFu, acc, off);
    }
    if (lane == 0) s_part[row_local][quarter] = acc;
    __syncthreads();

    // thread r combines the 4 quarter partials of local row r
    if (tid < ROWS_PER_BLOCK) {
        float dot = s_part[tid][0] + s_part[tid][1] +
                    s_part[tid][2] + s_part[tid][3];
        float score = dot * s_inv - thr[0];
        out[blockIdx.x * ROWS_PER_BLOCK + tid] = 1.0f / (1.0f + expf(-score));
    }
}

// ---------------------------------------------------------------------------
extern "C" void kernel_launch(void* const* d_in, const int* in_sizes, int n_in,
                              void* d_out, int out_size) {
    const float* x    = (const float*)d_in[0];
    const float* wc   = (const float*)d_in[1];
    const float* wint = (const float*)d_in[2];
    const float* thr  = (const float*)d_in[3];
    float* out = (float*)d_out;

    prep_weights_kernel<<<32, 256>>>(wc, wint);
    choquet_gemv_kernel<<<GRID, THREADS>>>(x, thr, out);
}

// round 11
// speedup vs baseline: 1.0028x; 1.0028x over previous
#include <cuda_runtime.h>
#include <math.h>

#define N_CRIT   128
#define N_PAIRS  8128          // 128*127/2
#define N_TOT    8256          // N_CRIT + N_PAIRS
#define N_VEC4   2064          // N_TOT / 4
#define N_HALF4  1032          // half-row in float4 (16512 B, 128B-aligned)
#define BATCH    16384
#define MIN_W    1e-7f
#define THREADS  512
#define ROWS_PER_BLOCK 8       // 16 warps: 2 warps per row (half-row each)
#define GRID     (BATCH / ROWS_PER_BLOCK)   // 2048

__device__ float g_w[N_TOT];      // constrained weights (wc_eff ‖ wint_eff)
__device__ float g_partial[32];   // per-prep-block weight-sum partials

// ---------------------------------------------------------------------------
// Prep: one pair per thread; per-block weight-sum partial into g_partial.
// grid = 32 x 256 (8192 >= 8128). No atomics, no memset needed.
// ---------------------------------------------------------------------------
__global__ __launch_bounds__(256)
void prep_weights_kernel(const float* __restrict__ wc,
                         const float* __restrict__ wint) {
    __shared__ float s_wc[N_CRIT];
    __shared__ float s_red[256];

    const int tid = threadIdx.x;
    float local = 0.0f;

    if (tid < N_CRIT) {
        float w = wc[tid];
        w = (w < 0.0f) ? MIN_W : w;
        s_wc[tid] = w;
        if (blockIdx.x == 0) {          // block 0 owns the wc part
            g_w[tid] = w;
            local += w;
        }
    }
    __syncthreads();

    const int p = blockIdx.x * 256 + tid;
    if (p < N_PAIRS) {
        // invert start(i) = i*(255-i)/2 via sqrt + integer fixup
        float fi = (255.0f - sqrtf(65025.0f - 8.0f * (float)p)) * 0.5f;
        int i = (int)fi;
        if (i > 126) i = 126;
        if (i < 0) i = 0;
        while (i * (255 - i) / 2 > p) --i;
        while ((i + 1) * (254 - i) / 2 <= p) ++i;
        int j = p - i * (255 - i) / 2 + i + 1;

        float w = fmaxf(wint[p], fmaxf(-s_wc[i], -s_wc[j]));
        g_w[N_CRIT + p] = w;
        local += w;
    }

    s_red[tid] = local;
    __syncthreads();
    #pragma unroll
    for (int off = 128; off > 0; off >>= 1) {
        if (tid < off) s_red[tid] += s_red[tid + off];
        __syncthreads();
    }
    if (tid == 0) g_partial[blockIdx.x] = s_red[0];
}

// ---------------------------------------------------------------------------
// GEMV (round-7 schedule): 2048 blocks x 512 threads. 8 rows per block,
// 2 warps per row, each warp streams an ALIGNED half-row (1032 float4,
// 32 unrolled iterations). Prologue: stage weights + warp-0 reduces the
// 32 prep partials; single __syncthreads.
// ---------------------------------------------------------------------------
__global__ __launch_bounds__(THREADS, 4)
void choquet_gemv_kernel(const float* __restrict__ x,
                         const float* __restrict__ thr,
                         float* __restrict__ out) {
    __shared__ __align__(16) float s_w[N_TOT];   // 33 KB
    __shared__ float s_part[16];                 // per-warp partials
    __shared__ float s_inv;

    const int tid = threadIdx.x;

    // stage weights (coalesced float4)
    const float4* gw4 = reinterpret_cast<const float4*>(g_w);
    float4* sw4 = reinterpret_cast<float4*>(s_w);
    #pragma unroll
    for (int k = tid; k < N_VEC4; k += THREADS) {
        sw4[k] = gw4[k];
    }
    // warp 0: reduce the 32 prep partials while others stage
    if (tid < 32) {
        float v = g_partial[tid];
        #pragma unroll
        for (int off = 16; off > 0; off >>= 1) {
            v += __shfl_xor_sync(0xFFFFFFFFu, v, off);
        }
        if (tid == 0) s_inv = 1.0f / v;
    }
    __syncthreads();

    const int warp = tid >> 5;
    const int lane = tid & 31;
    const int row_local = warp >> 1;          // 0..7
    const int half      = warp & 1;           // 0 or 1
    const int row  = blockIdx.x * ROWS_PER_BLOCK + row_local;

    const float4* xr = reinterpret_cast<const float4*>(x + (size_t)row * N_TOT);

    float acc = 0.0f;
    int k = half * N_HALF4 + lane;
    // 1032 float4 / 32 lanes = 32 full iterations + 8-lane tail
    #pragma unroll 4
    for (int it = 0; it < 32; ++it, k += 32) {
        float4 a = __ldcs(&xr[k]);            // streaming: read-once
        float4 b = sw4[k];
        acc = fmaf(a.x, b.x, acc);
        acc = fmaf(a.y, b.y, acc);
        acc = fmaf(a.z, b.z, acc);
        acc = fmaf(a.w, b.w, acc);
    }
    if (lane < 8) {                           // k = half*1032 + 1024 + lane
        float4 a = __ldcs(&xr[k]);
        float4 b = sw4[k];
        acc = fmaf(a.x, b.x, acc);
        acc = fmaf(a.y, b.y, acc);
        acc = fmaf(a.z, b.z, acc);
        acc = fmaf(a.w, b.w, acc);
    }

    // warp reduce
    #pragma unroll
    for (int off = 16; off > 0; off >>= 1) {
        acc += __shfl_xor_sync(0xFFFFFFFFu, acc, off);
    }
    if (lane == 0) s_part[warp] = acc;
    __syncthreads();

    // combine the two half-row partials and finish
    if (tid < ROWS_PER_BLOCK) {
        float dot = s_part[2 * tid] + s_part[2 * tid + 1];
        float score = dot * s_inv - thr[0];
        out[blockIdx.x * ROWS_PER_BLOCK + tid] = 1.0f / (1.0f + expf(-score));
    }
}

// ---------------------------------------------------------------------------
extern "C" void kernel_launch(void* const* d_in, const int* in_sizes, int n_in,
                              void* d_out, int out_size) {
    const float* x    = (const float*)d_in[0];
    const float* wc   = (const float*)d_in[1];
    const float* wint = (const float*)d_in[2];
    const float* thr  = (const float*)d_in[3];
    float* out = (float*)d_out;

    prep_weights_kernel<<<32, 256>>>(wc, wint);
    choquet_gemv_kernel<<<GRID, THREADS>>>(x, thr, out);
}

// round 13
// speedup vs baseline: 1.0454x; 1.0424x over previous
#include <cuda_runtime.h>
#include <math.h>

#define N_CRIT   128
#define N_PAIRS  8128          // 128*127/2
#define N_TOT    8256          // N_CRIT + N_PAIRS
#define N_VEC4   2064          // N_TOT / 4
#define N_HALF4  1032          // half-row in float4 (16512 B, 128B-aligned)
#define BATCH    16384
#define MIN_W    1e-7f
#define THREADS  512
#define ROWS_PER_BLOCK 8       // 16 warps: 2 warps per row (half-row each)
#define GRID     (BATCH / ROWS_PER_BLOCK)   // 2048

__device__ float g_w[N_TOT];      // constrained weights (wc_eff ‖ wint_eff)
__device__ float g_partial[32];   // per-prep-block weight-sum partials

// ---------------------------------------------------------------------------
// Prep: one pair per thread; per-block weight-sum partial into g_partial.
// grid = 32 x 256 (8192 >= 8128). No atomics, no memset.
// ---------------------------------------------------------------------------
__global__ __launch_bounds__(256)
void prep_weights_kernel(const float* __restrict__ wc,
                         const float* __restrict__ wint) {
    __shared__ float s_wc[N_CRIT];
    __shared__ float s_red[256];

    const int tid = threadIdx.x;
    float local = 0.0f;

    if (tid < N_CRIT) {
        float w = wc[tid];
        w = (w < 0.0f) ? MIN_W : w;
        s_wc[tid] = w;
        if (blockIdx.x == 0) {          // block 0 owns the wc part
            g_w[tid] = w;
            local += w;
        }
    }
    __syncthreads();

    const int p = blockIdx.x * 256 + tid;
    if (p < N_PAIRS) {
        // invert start(i) = i*(255-i)/2 via sqrt + integer fixup
        float fi = (255.0f - sqrtf(65025.0f - 8.0f * (float)p)) * 0.5f;
        int i = (int)fi;
        if (i > 126) i = 126;
        if (i < 0) i = 0;
        while (i * (255 - i) / 2 > p) --i;
        while ((i + 1) * (254 - i) / 2 <= p) ++i;
        int j = p - i * (255 - i) / 2 + i + 1;

        float w = fmaxf(wint[p], fmaxf(-s_wc[i], -s_wc[j]));
        g_w[N_CRIT + p] = w;
        local += w;
    }

    s_red[tid] = local;
    __syncthreads();
    #pragma unroll
    for (int off = 128; off > 0; off >>= 1) {
        if (tid < off) s_red[tid] += s_red[tid + off];
        __syncthreads();
    }
    if (tid == 0) g_partial[blockIdx.x] = s_red[0];
}

// ---------------------------------------------------------------------------
// GEMV: 2048 blocks x 512 threads. 8 rows/block, 2 warps per row, aligned
// half-row (1032 float4) per warp. The first two x loads are issued BEFORE
// the weight staging + barrier so DRAM is busy during the prologue.
// ---------------------------------------------------------------------------
__global__ __launch_bounds__(THREADS, 4)
void choquet_gemv_kernel(const float* __restrict__ x,
                         const float* __restrict__ thr,
                         float* __restrict__ out) {
    __shared__ __align__(16) float s_w[N_TOT];   // 33 KB
    __shared__ float s_part[16];                 // per-warp partials
    __shared__ float s_inv;

    const int tid  = threadIdx.x;
    const int warp = tid >> 5;
    const int lane = tid & 31;
    const int row_local = warp >> 1;          // 0..7
    const int half      = warp & 1;           // 0 or 1
    const int row  = blockIdx.x * ROWS_PER_BLOCK + row_local;
    const int kbase = half * N_HALF4 + lane;

    const float4* xr = reinterpret_cast<const float4*>(x + (size_t)row * N_TOT);

    // ---- prefetch first two x vectors (independent of s_w) ----
    float4 p0 = __ldcs(&xr[kbase]);
    float4 p1 = __ldcs(&xr[kbase + 32]);

    // ---- stage weights (coalesced float4) ----
    const float4* gw4 = reinterpret_cast<const float4*>(g_w);
    float4* sw4 = reinterpret_cast<float4*>(s_w);
    #pragma unroll
    for (int k = tid; k < N_VEC4; k += THREADS) {
        sw4[k] = gw4[k];
    }
    // warp 0: reduce the 32 prep partials while others stage
    if (tid < 32) {
        float v = g_partial[tid];
        #pragma unroll
        for (int off = 16; off > 0; off >>= 1) {
            v += __shfl_xor_sync(0xFFFFFFFFu, v, off);
        }
        if (tid == 0) s_inv = 1.0f / v;
    }
    __syncthreads();

    // ---- consume prefetched vectors ----
    float acc = 0.0f;
    {
        float4 b0 = sw4[kbase];
        acc = fmaf(p0.x, b0.x, acc);
        acc = fmaf(p0.y, b0.y, acc);
        acc = fmaf(p0.z, b0.z, acc);
        acc = fmaf(p0.w, b0.w, acc);
        float4 b1 = sw4[kbase + 32];
        acc = fmaf(p1.x, b1.x, acc);
        acc = fmaf(p1.y, b1.y, acc);
        acc = fmaf(p1.z, b1.z, acc);
        acc = fmaf(p1.w, b1.w, acc);
    }

    // ---- remaining 30 iterations + 8-lane tail ----
    int k = kbase + 64;
    #pragma unroll 5
    for (int it = 0; it < 30; ++it, k += 32) {
        float4 a = __ldcs(&xr[k]);            // streaming: read-once
        float4 b = sw4[k];
        acc = fmaf(a.x, b.x, acc);
        acc = fmaf(a.y, b.y, acc);
        acc = fmaf(a.z, b.z, acc);
        acc = fmaf(a.w, b.w, acc);
    }
    if (lane < 8) {                           // k = half*1032 + 1024 + lane
        float4 a = __ldcs(&xr[k]);
        float4 b = sw4[k];
        acc = fmaf(a.x, b.x, acc);
        acc = fmaf(a.y, b.y, acc);
        acc = fmaf(a.z, b.z, acc);
        acc = fmaf(a.w, b.w, acc);
    }

    // warp reduce
    #pragma unroll
    for (int off = 16; off > 0; off >>= 1) {
        acc += __shfl_xor_sync(0xFFFFFFFFu, acc, off);
    }
    if (lane == 0) s_part[warp] = acc;
    __syncthreads();

    // combine the two half-row partials and finish
    if (tid < ROWS_PER_BLOCK) {
        float dot = s_part[2 * tid] + s_part[2 * tid + 1];
        float score = dot * s_inv - thr[0];
        out[blockIdx.x * ROWS_PER_BLOCK + tid] = 1.0f / (1.0f + expf(-score));
    }
}

// ---------------------------------------------------------------------------
extern "C" void kernel_launch(void* const* d_in, const int* in_sizes, int n_in,
                              void* d_out, int out_size) {
    const float* x    = (const float*)d_in[0];
    const float* wc   = (const float*)d_in[1];
    const float* wint = (const float*)d_in[2];
    const float* thr  = (const float*)d_in[3];
    float* out = (float*)d_out;

    prep_weights_kernel<<<32, 256>>>(wc, wint);
    choquet_gemv_kernel<<<GRID, THREADS>>>(x, thr, out);
}